// round 16
// baseline (speedup 1.0000x reference)
#include <cuda_runtime.h>
#include <cstdint>

// Problem constants (fixed shapes)
#define B_  2
#define N_  6
#define Q_  900
#define C_  256
#define H_  116
#define W_  200
#define HW_ (H_ * W_)       // 23200, divisible by 4
#define EPS_ 1e-5f
#define BQ_ (B_ * Q_)       // 1800

// Scratch (no dynamic allocation allowed)
__device__ float g_agg[BQ_ * C_];   // mean-aggregated features

// Uniform-index select from float4 (s is warp-uniform -> predicated SELs)
__device__ __forceinline__ float sel4(float4 f, int s) {
    float v = f.x;
    if (s == 1) v = f.y;
    else if (s == 2) v = f.z;
    else if (s == 3) v = f.w;
    return v;
}

// packed f32x2 fma: d = a*b + d elementwise on (lo,hi) pairs in 64-bit regs
__device__ __forceinline__ void ffma2(unsigned long long& d,
                                      unsigned long long a,
                                      unsigned long long b) {
    asm("fma.rn.f32x2 %0, %1, %2, %0;" : "+l"(d) : "l"(a), "l"(b));
}

// swap the two 32-bit halves of a 64-bit pair
__device__ __forceinline__ unsigned long long swap2(unsigned long long p) {
    return (p >> 32) | (p << 32);
}

// ---------------------------------------------------------------------------
// Fused kernel: projection (threads 0..5) + bilinear gather + camera mean
// one block per (b,q); 64 threads; 4 channels/thread (tid,+64,+128,+192)
// [identical to the R6/R9/R13/R15 best-known gather]
// ---------------------------------------------------------------------------
__global__ __launch_bounds__(64) void gather_kernel(
    const float* __restrict__ feats,     // (B,N,C,H,W)
    const float* __restrict__ ref_pts,   // (B,Q,3)
    const float* __restrict__ lidar2img) // (B,N,4,4)
{
    __shared__ float4 sw[N_];
    __shared__ int4   sb[N_];

    int bq  = blockIdx.x;
    int b   = bq / Q_;
    int q   = bq % Q_;
    int tid = threadIdx.x;

    if (tid < N_) {
        int n = tid;
        const float* rp = ref_pts + ((size_t)b * Q_ + q) * 3;
        float px = rp[0], py = rp[1], pz = rp[2];

        const float* M = lidar2img + ((size_t)b * N_ + n) * 16;
        float xc = M[0]  * px + M[1]  * py + M[2]  * pz + M[3];
        float yc = M[4]  * px + M[5]  * py + M[6]  * pz + M[7];
        float zc = M[8]  * px + M[9]  * py + M[10] * pz + M[11];

        float denom = fabsf(zc) + EPS_;
        float x2d = xc / denom;
        float y2d = yc / denom;

        float gx = x2d / (float)(W_ - 1) * 2.0f - 1.0f;
        float gy = y2d / (float)(H_ - 1) * 2.0f - 1.0f;

        bool front  = zc > EPS_;
        bool in_img = fmaxf(fabsf(gx), fabsf(gy)) <= 1.0f;
        int  valid  = (front && in_img) ? 1 : 0;
        float vv    = valid ? (1.0f / (float)N_) : 0.0f;

        float x = ((gx + 1.0f) * (float)W_ - 1.0f) * 0.5f;
        float y = ((gy + 1.0f) * (float)H_ - 1.0f) * 0.5f;
        x = fminf(fmaxf(x, -100.0f), (float)(W_ + 100));
        y = fminf(fmaxf(y, -100.0f), (float)(H_ + 100));

        float x0f = floorf(x), y0f = floorf(y);
        float wx = x - x0f, wy = y - y0f;
        int x0 = (int)x0f, y0 = (int)y0f;
        int x1 = x0 + 1,   y1 = y0 + 1;

        float v00 = (x0 >= 0 && x0 < W_ && y0 >= 0 && y0 < H_) ? 1.0f : 0.0f;
        float v10 = (x1 >= 0 && x1 < W_ && y0 >= 0 && y0 < H_) ? 1.0f : 0.0f;
        float v01 = (x0 >= 0 && x0 < W_ && y1 >= 0 && y1 < H_) ? 1.0f : 0.0f;
        float v11 = (x1 >= 0 && x1 < W_ && y1 >= 0 && y1 < H_) ? 1.0f : 0.0f;

        float4 w;
        w.x = (1.0f - wx) * (1.0f - wy) * v00 * vv;
        w.y = wx          * (1.0f - wy) * v10 * vv;
        w.z = (1.0f - wx) * wy          * v01 * vv;
        w.w = wx          * wy          * v11 * vv;

        int cx0 = min(max(x0, 0), W_ - 1);
        int cx1 = min(max(x1, 0), W_ - 1);
        int cy0 = min(max(y0, 0), H_ - 1);
        int cy1 = min(max(y1, 0), H_ - 1);

        int i0 = cy0 * W_ + cx0;
        int i1 = cy0 * W_ + cx1;
        int j0 = cy1 * W_ + cx0;

        int base_t = i0 & ~3;
        int s0 = i0 - base_t;
        int s1 = i1 - base_t;
        int base_b = j0 - s0;

        sw[n] = w;
        sb[n] = make_int4(base_t, base_b, s0 | (s1 << 8), valid);
    }
    __syncthreads();

    float acc0 = 0.0f, acc1 = 0.0f, acc2 = 0.0f, acc3 = 0.0f;
#pragma unroll
    for (int n = 0; n < N_; n++) {
        int4 ib = sb[n];
        if (!ib.w) continue;
        float4 w = sw[n];
        const float* p0 = feats + ((size_t)((b * N_ + n) * C_) + tid) * HW_;
        const float* p1 = p0 + (size_t)64  * HW_;
        const float* p2 = p0 + (size_t)128 * HW_;
        const float* p3 = p0 + (size_t)192 * HW_;

        float4 t0 = *reinterpret_cast<const float4*>(p0 + ib.x);
        float4 b0v = *reinterpret_cast<const float4*>(p0 + ib.y);
        float4 t1 = *reinterpret_cast<const float4*>(p1 + ib.x);
        float4 b1v = *reinterpret_cast<const float4*>(p1 + ib.y);
        float4 t2 = *reinterpret_cast<const float4*>(p2 + ib.x);
        float4 b2v = *reinterpret_cast<const float4*>(p2 + ib.y);
        float4 t3 = *reinterpret_cast<const float4*>(p3 + ib.x);
        float4 b3v = *reinterpret_cast<const float4*>(p3 + ib.y);

        int s0 = ib.z & 0xff;
        int s1 = ib.z >> 8;

        float vt0a = sel4(t0, s0), vb0a = sel4(b0v, s0);
        float vt0b = sel4(t1, s0), vb0b = sel4(b1v, s0);
        float vt0c = sel4(t2, s0), vb0c = sel4(b2v, s0);
        float vt0d = sel4(t3, s0), vb0d = sel4(b3v, s0);
        float vt1a, vb1a, vt1b, vb1b, vt1c, vb1c, vt1d, vb1d;
        if (s1 < 4) {
            vt1a = sel4(t0, s1);  vb1a = sel4(b0v, s1);
            vt1b = sel4(t1, s1);  vb1b = sel4(b1v, s1);
            vt1c = sel4(t2, s1);  vb1c = sel4(b2v, s1);
            vt1d = sel4(t3, s1);  vb1d = sel4(b3v, s1);
        } else {
            vt1a = __ldg(p0 + ib.x + 4);  vb1a = __ldg(p0 + ib.y + 4);
            vt1b = __ldg(p1 + ib.x + 4);  vb1b = __ldg(p1 + ib.y + 4);
            vt1c = __ldg(p2 + ib.x + 4);  vb1c = __ldg(p2 + ib.y + 4);
            vt1d = __ldg(p3 + ib.x + 4);  vb1d = __ldg(p3 + ib.y + 4);
        }
        acc0 = fmaf(w.x, vt0a, acc0);
        acc0 = fmaf(w.y, vt1a, acc0);
        acc0 = fmaf(w.z, vb0a, acc0);
        acc0 = fmaf(w.w, vb1a, acc0);
        acc1 = fmaf(w.x, vt0b, acc1);
        acc1 = fmaf(w.y, vt1b, acc1);
        acc1 = fmaf(w.z, vb0b, acc1);
        acc1 = fmaf(w.w, vb1b, acc1);
        acc2 = fmaf(w.x, vt0c, acc2);
        acc2 = fmaf(w.y, vt1c, acc2);
        acc2 = fmaf(w.z, vb0c, acc2);
        acc2 = fmaf(w.w, vb1c, acc2);
        acc3 = fmaf(w.x, vt0d, acc3);
        acc3 = fmaf(w.y, vt1d, acc3);
        acc3 = fmaf(w.z, vb0d, acc3);
        acc3 = fmaf(w.w, vb1d, acc3);
    }
    float* outp = &g_agg[(size_t)bq * C_ + tid];
    outp[0]   = acc0;
    outp[64]  = acc1;
    outp[128] = acc2;
    outp[192] = acc3;
}

// ---------------------------------------------------------------------------
// GEMM: out = agg @ W^T + bias  (M=1800, N=256, K=256)
// 32x32 tiles, grid 57x8 = 456 blocks, 256 threads = 8 warp-private k-groups.
// Each warp: K-chunk 32 (2 BK=16 tiles, SEQUENTIAL loads — no live prefetch
// registers), 4x8 diag-pair microtile: per k-step 3 LDS.128 -> 32 MACs
// (1.5 B/MAC) as 16 FFMA2 + 4 swaps. __launch_bounds__(256,3) caps regs for
// 3 blocks/SM. Partials reduced via smem overlay, deterministic order.
// ---------------------------------------------------------------------------
#define BM 32
#define BN 32
#define BK 16
#define KG 8
#define KCH (C_ / KG)      // 32
#define NTg (KCH / BK)     // 2 tiles per warp
#define AST 36             // padded row stride (floats); 144B = 16 mod 128

__global__ __launch_bounds__(256, 3) void gemm_kernel(const float* __restrict__ Wm,   // (256,256) row-major
                                                      const float* __restrict__ bias,
                                                      float* __restrict__ out)        // (1800,256)
{
    __shared__ union {
        struct {
            float As[KG][BK][AST];   // 18 KB
            float Bs[KG][BK][AST];   // 18 KB
        } t;
        float Red[KG][BM * BN];      // 32 KB (overlaid; tiles dead before use)
    } sm;

    const int M = BQ_;
    int t  = threadIdx.x;       // 0..255
    int w  = t >> 5;            // warp = k-group 0..7
    int u  = t & 31;            // lane
    int tm = u >> 2;            // 0..7 -> rows tm*4..+3
    int tn = u & 3;             // 0..3 -> cols tn*8..+7

    int bM = blockIdx.x * BM;
    int bN = blockIdx.y * BN;
    int koff = w * KCH;

    // loader mapping: 128 float4 per tile, 4 per thread (rows lr+0,8,16,24)
    int lr = u >> 2;            // 0..7
    int k4 = (u & 3) * 4;       // 0,4,8,12

    const float* Abase = &g_agg[(size_t)(bM + lr) * C_ + koff + k4];
    const float* Bbase = &Wm[(size_t)(bN + lr) * C_ + koff + k4];

    // accumulators: rp in {0,1} row-pairs, jq in {0..3} col-pairs
    unsigned long long accd[2][4], accx[2][4];
#pragma unroll
    for (int i = 0; i < 2; i++)
#pragma unroll
        for (int j = 0; j < 4; j++) { accd[i][j] = 0ull; accx[i][j] = 0ull; }

#pragma unroll
    for (int tile = 0; tile < NTg; tile++) {
        // load this tile gmem -> smem (short-lived registers only)
#pragma unroll
        for (int i = 0; i < 4; i++) {
            int row = lr + i * 8;
            float4 a = make_float4(0.f, 0.f, 0.f, 0.f);
            if (bM + row < M)
                a = *reinterpret_cast<const float4*>(Abase + (size_t)(i * 8) * C_ + tile * BK);
            float4 b = *reinterpret_cast<const float4*>(Bbase + (size_t)(i * 8) * C_ + tile * BK);
            float va[4] = {a.x, a.y, a.z, a.w};
            float vb[4] = {b.x, b.y, b.z, b.w};
#pragma unroll
            for (int j = 0; j < 4; j++) {
                sm.t.As[w][k4 + j][row] = va[j];
                sm.t.Bs[w][k4 + j][row] = vb[j];
            }
        }
        __syncwarp();

        // compute BK k-steps: 3 LDS.128 -> 16 FFMA2 each
#pragma unroll
        for (int kk = 0; kk < BK; kk++) {
            ulonglong2 fa  = *reinterpret_cast<const ulonglong2*>(&sm.t.As[w][kk][tm * 4]);
            ulonglong2 fb0 = *reinterpret_cast<const ulonglong2*>(&sm.t.Bs[w][kk][tn * 8]);
            ulonglong2 fb1 = *reinterpret_cast<const ulonglong2*>(&sm.t.Bs[w][kk][tn * 8 + 4]);
            unsigned long long bq0 = fb0.x, bq1 = fb0.y, bq2 = fb1.x, bq3 = fb1.y;
            unsigned long long bs0 = swap2(bq0), bs1 = swap2(bq1);
            unsigned long long bs2 = swap2(bq2), bs3 = swap2(bq3);
            ffma2(accd[0][0], fa.x, bq0);
            ffma2(accx[0][0], fa.x, bs0);
            ffma2(accd[0][1], fa.x, bq1);
            ffma2(accx[0][1], fa.x, bs1);
            ffma2(accd[0][2], fa.x, bq2);
            ffma2(accx[0][2], fa.x, bs2);
            ffma2(accd[0][3], fa.x, bq3);
            ffma2(accx[0][3], fa.x, bs3);
            ffma2(accd[1][0], fa.y, bq0);
            ffma2(accx[1][0], fa.y, bs0);
            ffma2(accd[1][1], fa.y, bq1);
            ffma2(accx[1][1], fa.y, bs1);
            ffma2(accd[1][2], fa.y, bq2);
            ffma2(accx[1][2], fa.y, bs2);
            ffma2(accd[1][3], fa.y, bq3);
            ffma2(accx[1][3], fa.y, bs3);
        }

        // single buffer: make sure the warp is done before overwriting
        if (tile + 1 < NTg) __syncwarp();
    }

    // ALL warps done with tiles before overlaying Red on them
    __syncthreads();

    // unpack diagonal pairs into plain partial layout in smem
#pragma unroll
    for (int rp = 0; rp < 2; rp++) {
#pragma unroll
        for (int jq = 0; jq < 4; jq++) {
            float2 d = *reinterpret_cast<float2*>(&accd[rp][jq]);
            float2 x = *reinterpret_cast<float2*>(&accx[rp][jq]);
            int r0 = tm * 4 + rp * 2;
            int c0 = tn * 8 + jq * 2;
            // C[r0][c0]=d.x, C[r0][c1]=x.x, C[r1][c0]=x.y, C[r1][c1]=d.y
            *reinterpret_cast<float2*>(&sm.Red[w][r0 * BN + c0])       = make_float2(d.x, x.x);
            *reinterpret_cast<float2*>(&sm.Red[w][(r0 + 1) * BN + c0]) = make_float2(x.y, d.y);
        }
    }
    __syncthreads();

    // reduce 8 partials + bias, store (256 threads x 4 floats = 1024 outputs)
    {
        int e   = t * 4;            // 0..1020
        int row = t >> 3;           // e / 32
        int col = (t & 7) * 4;      // e % 32
        float4 s = *reinterpret_cast<const float4*>(&sm.Red[0][e]);
#pragma unroll
        for (int g = 1; g < KG; g++) {
            float4 p = *reinterpret_cast<const float4*>(&sm.Red[g][e]);
            s.x += p.x; s.y += p.y; s.z += p.z; s.w += p.w;
        }
        float4 bb = *reinterpret_cast<const float4*>(&bias[bN + col]);
        s.x += bb.x; s.y += bb.y; s.z += bb.z; s.w += bb.w;
        int gm = bM + row;
        if (gm < M)
            *reinterpret_cast<float4*>(&out[(size_t)gm * C_ + bN + col]) = s;
    }
}

// ---------------------------------------------------------------------------
// launch
// inputs: 0=query (unused), 1=reference_points, 2=image_features,
//         3=lidar2img, 4=W_out, 5=b_out; output float32 (B,Q,C)
// ---------------------------------------------------------------------------
extern "C" void kernel_launch(void* const* d_in, const int* in_sizes, int n_in,
                              void* d_out, int out_size)
{
    const float* ref_pts   = (const float*)d_in[1];
    const float* feats     = (const float*)d_in[2];
    const float* lidar2img = (const float*)d_in[3];
    const float* Wm        = (const float*)d_in[4];
    const float* bias      = (const float*)d_in[5];
    float* out = (float*)d_out;

    gather_kernel<<<BQ_, 64>>>(feats, ref_pts, lidar2img);
    dim3 gg((BQ_ + BM - 1) / BM, C_ / BN);   // 57 x 8 = 456 blocks
    gemm_kernel<<<gg, 256>>>(Wm, bias, out);
}